// round 11
// baseline (speedup 1.0000x reference)
#include <cuda_runtime.h>
#include <cstdint>

// Problem constants
#define NMAX    100000
#define IN_DIM  32
#define HID     64
#define NGRAPHS 128
#define LAT     32
#define LDA     68   // padded row stride for activation tiles (bank shift 4/row)

// Scratch (device globals — allocation-free rule)
__device__ __align__(16) float g_h[(size_t)NMAX * HID];
__device__ __align__(16) float g_agg[(size_t)NMAX * HID];
__device__ __align__(16) float g_pooled[NGRAPHS * HID];

__device__ __forceinline__ void red_add_v4(float* p, float4 v) {
    asm volatile("red.global.add.v4.f32 [%0], {%1,%2,%3,%4};"
                 :: "l"(p), "f"(v.x), "f"(v.y), "f"(v.z), "f"(v.w)
                 : "memory");
}

// ---- packed fp32x2 helpers (FFMA2: 2x flops per issue slot) -------------
typedef unsigned long long u64t;

__device__ __forceinline__ void fma2(u64t& d, u64t a, u64t b) {
    asm("fma.rn.f32x2 %0, %1, %2, %0;" : "+l"(d) : "l"(a), "l"(b));
}
__device__ __forceinline__ u64t pack2(float x, float y) {
    u64t r;
    asm("mov.b64 %0, {%1, %2};" : "=l"(r) : "f"(x), "f"(y));
    return r;
}
__device__ __forceinline__ void unpack2(u64t v, float& x, float& y) {
    asm("mov.b64 {%0, %1}, %2;" : "=f"(x), "=f"(y) : "l"(v));
}
// VOLATILE + memory clobber: sW is overwritten (w1 -> w2) between phases.
// A non-volatile asm is "pure" and the compiler CSE'd phase-2 loads with
// phase-1 loads of the same address -> phase 2 used w1 (rel_err 1.59 bug).
__device__ __forceinline__ void lds_w2(uint32_t addr, u64t& w01, u64t& w23) {
    asm volatile("ld.shared.v2.b64 {%0, %1}, [%2];"
                 : "=l"(w01), "=l"(w23) : "r"(addr) : "memory");
}
__device__ __forceinline__ uint32_t smem_u32(const void* p) {
    uint32_t a;
    asm("{ .reg .u64 t; cvta.to.shared.u64 t, %1; cvt.u32.u64 %0, t; }"
        : "=r"(a) : "l"(p));
    return a;
}

// ===========================================================================
// Zero kernels
// ===========================================================================
__global__ void k_zero_agg(int n4) {
    int i = blockIdx.x * blockDim.x + threadIdx.x;
    if (i < n4) reinterpret_cast<float4*>(g_agg)[i] = make_float4(0.f, 0.f, 0.f, 0.f);
}

__global__ void k_zero_pooled() {
    int i = blockIdx.x * blockDim.x + threadIdx.x;
    if (i < NGRAPHS * HID / 4)
        reinterpret_cast<float4*>(g_pooled)[i] = make_float4(0.f, 0.f, 0.f, 0.f);
}

// ===========================================================================
// Input projection: h = x @ w_in + b_in   [N,32] @ [32,64]
// ===========================================================================
__global__ __launch_bounds__(256) void k_proj(const float* __restrict__ x,
                                              const float* __restrict__ w_in,
                                              const float* __restrict__ b_in,
                                              int nNodes) {
    __shared__ __align__(16) float sX[64 * IN_DIM];
    __shared__ __align__(16) float sW[IN_DIM * HID];
    int tid = threadIdx.x;
    int nb = blockIdx.x * 64;

    for (int i = tid; i < 64 * IN_DIM; i += 256) {
        int n = nb + i / IN_DIM;
        sX[i] = (n < nNodes) ? x[(size_t)nb * IN_DIM + i] : 0.f;
    }
    for (int i = tid; i < IN_DIM * HID; i += 256) sW[i] = w_in[i];
    __syncthreads();

    int fq = tid & 15, ng = tid >> 4;
    float acc[4][4];
    float4 bb = *reinterpret_cast<const float4*>(b_in + 4 * fq);
#pragma unroll
    for (int n = 0; n < 4; n++) {
        acc[n][0] = bb.x; acc[n][1] = bb.y; acc[n][2] = bb.z; acc[n][3] = bb.w;
    }
#pragma unroll
    for (int k = 0; k < IN_DIM; k += 4) {
        float4 w0 = *reinterpret_cast<const float4*>(&sW[(k + 0) * HID + 4 * fq]);
        float4 w1 = *reinterpret_cast<const float4*>(&sW[(k + 1) * HID + 4 * fq]);
        float4 w2 = *reinterpret_cast<const float4*>(&sW[(k + 2) * HID + 4 * fq]);
        float4 w3 = *reinterpret_cast<const float4*>(&sW[(k + 3) * HID + 4 * fq]);
#pragma unroll
        for (int n = 0; n < 4; n++) {
            float4 a = *reinterpret_cast<const float4*>(&sX[(ng * 4 + n) * IN_DIM + k]);
            acc[n][0] += a.x * w0.x + a.y * w1.x + a.z * w2.x + a.w * w3.x;
            acc[n][1] += a.x * w0.y + a.y * w1.y + a.z * w2.y + a.w * w3.y;
            acc[n][2] += a.x * w0.z + a.y * w1.z + a.z * w2.z + a.w * w3.z;
            acc[n][3] += a.x * w0.w + a.y * w1.w + a.z * w2.w + a.w * w3.w;
        }
    }
#pragma unroll
    for (int n = 0; n < 4; n++) {
        int node = nb + ng * 4 + n;
        if (node < nNodes)
            *reinterpret_cast<float4*>(&g_h[(size_t)node * HID + 4 * fq]) =
                make_float4(acc[n][0], acc[n][1], acc[n][2], acc[n][3]);
    }
}

// ===========================================================================
// Edge scatter: agg[dst] += h[src].  16 threads/edge, vec4 reductions.
// ===========================================================================
__global__ __launch_bounds__(256) void k_scatter(const int* __restrict__ ei,
                                                 int nEdges, int nNodes) {
    long long t = (long long)blockIdx.x * blockDim.x + threadIdx.x;
    int e = (int)(t >> 4);
    int lane = (int)(t & 15);
    if (e >= nEdges) return;
    int src = __ldg(&ei[e]);
    int dst = __ldg(&ei[(size_t)nEdges + e]);
    if ((unsigned)src >= (unsigned)nNodes || (unsigned)dst >= (unsigned)nNodes) return;
    float4 v = *reinterpret_cast<const float4*>(&g_h[(size_t)src * HID + 4 * lane]);
    red_add_v4(&g_agg[(size_t)dst * HID + 4 * lane], v);
}

// ===========================================================================
// Fused GIN MLP with packed f32x2 FMA:
//   h = relu(relu((h+agg)@w1+b1)@w2+b2) + h ; also zeroes g_agg.
// 256 threads, tile 64 nodes x 64 cols; thread tile 2 rows x 8 cols.
// ===========================================================================
// Packed GEMM core: acc{0,1}[j] over 8 cols for rows r0,r1 against sW (stride 64)
__device__ __forceinline__ void gemm_packed(const float* __restrict__ sIn,
                                            uint32_t swAddr,  // &sW[c0] as smem addr
                                            int r0, int r1,
                                            u64t acc0[4], u64t acc1[4]) {
#pragma unroll
    for (int k = 0; k < HID; k += 4) {
        float4 a0v = *reinterpret_cast<const float4*>(&sIn[r0 * LDA + k]);
        float4 a1v = *reinterpret_cast<const float4*>(&sIn[r1 * LDA + k]);
        float a0s[4] = {a0v.x, a0v.y, a0v.z, a0v.w};
        float a1s[4] = {a1v.x, a1v.y, a1v.z, a1v.w};
#pragma unroll
        for (int kk = 0; kk < 4; kk++) {
            u64t pa0 = pack2(a0s[kk], a0s[kk]);
            u64t pa1 = pack2(a1s[kk], a1s[kk]);
            uint32_t wa = swAddr + (uint32_t)((k + kk) * HID * 4);
            u64t w01, w23, w45, w67;
            lds_w2(wa, w01, w23);
            lds_w2(wa + 16, w45, w67);
            fma2(acc0[0], pa0, w01); fma2(acc0[1], pa0, w23);
            fma2(acc0[2], pa0, w45); fma2(acc0[3], pa0, w67);
            fma2(acc1[0], pa1, w01); fma2(acc1[1], pa1, w23);
            fma2(acc1[2], pa1, w45); fma2(acc1[3], pa1, w67);
        }
    }
}

__global__ __launch_bounds__(256) void k_mlp(const float* __restrict__ w1,
                                             const float* __restrict__ b1,
                                             const float* __restrict__ w2,
                                             const float* __restrict__ b2,
                                             int nNodes) {
    __shared__ __align__(16) float sW[HID * HID];    // 16 KB
    __shared__ __align__(16) float sIn[64 * LDA];    // 17.4 KB (reused as act buffer)
    int tid = threadIdx.x;
    int nb = blockIdx.x * 64;

    // stage w1 + input tile (h+agg), zero agg
    for (int i = tid; i < HID * HID; i += 256) sW[i] = w1[i];
    for (int i = tid; i < 1024; i += 256) {          // 64 rows x 16 float4
        int r = i >> 4;
        int c4 = (i & 15) << 2;
        int node = nb + r;
        float4 v = make_float4(0.f, 0.f, 0.f, 0.f);
        if (node < nNodes) {
            size_t gi = (size_t)node * HID + c4;
            float4 a = *(const float4*)&g_h[gi];
            float4 g = *(const float4*)&g_agg[gi];
            *(float4*)&g_agg[gi] = make_float4(0.f, 0.f, 0.f, 0.f);
            v = make_float4(a.x + g.x, a.y + g.y, a.z + g.z, a.w + g.w);
        }
        *(float4*)&sIn[r * LDA + c4] = v;
    }
    __syncthreads();

    int cg = tid & 7, rp = tid >> 3;
    int r0 = rp * 2, r1 = r0 + 1;
    int c0 = cg * 8;
    uint32_t swAddr = smem_u32(sW) + (uint32_t)(c0 * 4);

    u64t acc0[4], acc1[4];

    // ---- phase 1: mid = relu(in @ w1 + b1) ----
#pragma unroll
    for (int j = 0; j < 4; j++) {
        float bx = b1[c0 + 2 * j], by = b1[c0 + 2 * j + 1];
        acc0[j] = pack2(bx, by);
        acc1[j] = pack2(bx, by);
    }
    gemm_packed(sIn, swAddr, r0, r1, acc0, acc1);
    __syncthreads();   // all reads of sIn/sW done

    {
        float v[2][8];
#pragma unroll
        for (int j = 0; j < 4; j++) {
            unpack2(acc0[j], v[0][2 * j], v[0][2 * j + 1]);
            unpack2(acc1[j], v[1][2 * j], v[1][2 * j + 1]);
        }
#pragma unroll
        for (int rr = 0; rr < 2; rr++) {
            int r = r0 + rr;
            *(float4*)&sIn[r * LDA + c0] =
                make_float4(fmaxf(v[rr][0], 0.f), fmaxf(v[rr][1], 0.f),
                            fmaxf(v[rr][2], 0.f), fmaxf(v[rr][3], 0.f));
            *(float4*)&sIn[r * LDA + c0 + 4] =
                make_float4(fmaxf(v[rr][4], 0.f), fmaxf(v[rr][5], 0.f),
                            fmaxf(v[rr][6], 0.f), fmaxf(v[rr][7], 0.f));
        }
    }
    for (int i = tid; i < HID * HID; i += 256) sW[i] = w2[i];
    __syncthreads();

    // ---- phase 2: h = relu(mid @ w2 + b2) + h_skip ----
#pragma unroll
    for (int j = 0; j < 4; j++) {
        float bx = b2[c0 + 2 * j], by = b2[c0 + 2 * j + 1];
        acc0[j] = pack2(bx, by);
        acc1[j] = pack2(bx, by);
    }
    gemm_packed(sIn, swAddr, r0, r1, acc0, acc1);

    {
        float v[2][8];
#pragma unroll
        for (int j = 0; j < 4; j++) {
            unpack2(acc0[j], v[0][2 * j], v[0][2 * j + 1]);
            unpack2(acc1[j], v[1][2 * j], v[1][2 * j + 1]);
        }
#pragma unroll
        for (int rr = 0; rr < 2; rr++) {
            int node = nb + r0 + rr;
            if (node < nNodes) {
                size_t gb = (size_t)node * HID + c0;
                float4 s0 = *(const float4*)&g_h[gb];
                float4 s1 = *(const float4*)&g_h[gb + 4];
                *(float4*)&g_h[gb] =
                    make_float4(fmaxf(v[rr][0], 0.f) + s0.x, fmaxf(v[rr][1], 0.f) + s0.y,
                                fmaxf(v[rr][2], 0.f) + s0.z, fmaxf(v[rr][3], 0.f) + s0.w);
                *(float4*)&g_h[gb + 4] =
                    make_float4(fmaxf(v[rr][4], 0.f) + s1.x, fmaxf(v[rr][5], 0.f) + s1.y,
                                fmaxf(v[rr][6], 0.f) + s1.z, fmaxf(v[rr][7], 0.f) + s1.w);
            }
        }
    }
}

// ===========================================================================
// Global add-pool + final projection
// ===========================================================================
__global__ __launch_bounds__(256) void k_pool(const int* __restrict__ batch,
                                              int nNodes) {
    long long t = (long long)blockIdx.x * blockDim.x + threadIdx.x;
    int node = (int)(t >> 4);
    int lane = (int)(t & 15);
    if (node >= nNodes) return;
    int g = __ldg(&batch[node]);
    if ((unsigned)g >= NGRAPHS) return;
    float4 v = *reinterpret_cast<const float4*>(&g_h[(size_t)node * HID + 4 * lane]);
    red_add_v4(&g_pooled[g * HID + 4 * lane], v);
}

__global__ __launch_bounds__(256) void k_final(const float* __restrict__ w_fc,
                                               const float* __restrict__ b_fc,
                                               float* __restrict__ out) {
    int t = blockIdx.x * blockDim.x + threadIdx.x;
    if (t >= NGRAPHS * LAT) return;
    int g = t >> 5;
    int l = t & 31;
    float acc = b_fc[l];
#pragma unroll
    for (int k = 0; k < HID; k++)
        acc += g_pooled[g * HID + k] * w_fc[k * LAT + l];
    out[t] = acc;
}

// ===========================================================================
// Launch
// ===========================================================================
extern "C" void kernel_launch(void* const* d_in, const int* in_sizes, int n_in,
                              void* d_out, int out_size) {
    const float* x    = (const float*)d_in[0];
    const int*   ei   = (const int*)d_in[1];
    const int*   batch= (const int*)d_in[2];
    const float* w_in = (const float*)d_in[3];
    const float* b_in = (const float*)d_in[4];
    const float* w1   = (const float*)d_in[5];
    const float* b1   = (const float*)d_in[6];
    const float* w2   = (const float*)d_in[7];
    const float* b2   = (const float*)d_in[8];
    const float* w_fc = (const float*)d_in[9];
    const float* b_fc = (const float*)d_in[10];
    float* out = (float*)d_out;

    int nNodes = in_sizes[0] / IN_DIM;
    int nEdges = in_sizes[1] / 2;
    if (nNodes > NMAX) nNodes = NMAX;

    int nodeBlocks = (nNodes + 63) / 64;
    int aggN4 = nNodes * HID / 4;
    int zeroBlocks = (aggN4 + 255) / 256;
    long long scatterThreads = (long long)nEdges * 16;
    int scatterBlocks = (int)((scatterThreads + 255) / 256);
    long long poolThreads = (long long)nNodes * 16;
    int poolBlocks = (int)((poolThreads + 255) / 256);

    k_zero_pooled<<<(NGRAPHS * HID / 4 + 255) / 256, 256>>>();
    k_proj<<<nodeBlocks, 256>>>(x, w_in, b_in, nNodes);

    for (int i = 0; i < 3; i++) {
        if (i == 0) k_zero_agg<<<zeroBlocks, 256>>>(aggN4);  // later layers: mlp zeroes agg
        k_scatter<<<scatterBlocks, 256>>>(ei, nEdges, nNodes);
        k_mlp<<<nodeBlocks, 256>>>(w1 + (size_t)i * HID * HID, b1 + (size_t)i * HID,
                                   w2 + (size_t)i * HID * HID, b2 + (size_t)i * HID,
                                   nNodes);
    }

    k_pool<<<poolBlocks, 256>>>(batch, nNodes);
    k_final<<<(NGRAPHS * LAT + 255) / 256, 256>>>(w_fc, b_fc, out);
}

// round 13
// speedup vs baseline: 1.9167x; 1.9167x over previous
#include <cuda_runtime.h>
#include <cstdint>

// Problem constants
#define NMAX    100000
#define EMAX    1000000
#define IN_DIM  32
#define HID     64
#define NGRAPHS 128
#define LAT     32

// Scratch (device globals — allocation-free rule)
__device__ __align__(16) float g_hA[(size_t)NMAX * HID];
__device__ __align__(16) float g_hB[(size_t)NMAX * HID];
__device__ __align__(16) float g_pooled[NGRAPHS * HID];
__device__ int g_deg[NMAX];
__device__ int g_off[NMAX];
__device__ int g_cur[NMAX];
__device__ int g_csr[EMAX];
__device__ int g_part[128];

__device__ __forceinline__ void red_add_v4(float* p, float4 v) {
    asm volatile("red.global.add.v4.f32 [%0], {%1,%2,%3,%4};"
                 :: "l"(p), "f"(v.x), "f"(v.y), "f"(v.z), "f"(v.w)
                 : "memory");
}

// ===========================================================================
// Zero / CSR-build kernels
// ===========================================================================
__global__ void k_zero_pooled() {
    int i = blockIdx.x * blockDim.x + threadIdx.x;
    if (i < NGRAPHS * HID / 4)
        reinterpret_cast<float4*>(g_pooled)[i] = make_float4(0.f, 0.f, 0.f, 0.f);
}

__global__ void k_zero_deg(int n) {
    int i = blockIdx.x * blockDim.x + threadIdx.x;
    if (i < n) g_deg[i] = 0;
}

__global__ void k_hist(const int* __restrict__ ei, int nEdges, int nNodes) {
    int e = blockIdx.x * blockDim.x + threadIdx.x;
    if (e >= nEdges) return;
    int src = __ldg(&ei[e]);
    int dst = __ldg(&ei[(size_t)nEdges + e]);
    if ((unsigned)src >= (unsigned)nNodes || (unsigned)dst >= (unsigned)nNodes) return;
    atomicAdd(&g_deg[dst], 1);
}

// chunk-local exclusive scan (1024/chunk) + chunk totals
__global__ __launch_bounds__(1024) void k_scan1(int n) {
    __shared__ int s[1024];
    int t = threadIdx.x;
    int i = blockIdx.x * 1024 + t;
    int v = (i < n) ? g_deg[i] : 0;
    s[t] = v;
    __syncthreads();
    for (int off = 1; off < 1024; off <<= 1) {
        int x = (t >= off) ? s[t - off] : 0;
        __syncthreads();
        s[t] += x;
        __syncthreads();
    }
    if (i < n) g_off[i] = s[t] - v;        // exclusive within chunk
    if (t == 1023) g_part[blockIdx.x] = s[1023];
}

// exclusive scan of chunk totals (<=128 chunks)
__global__ __launch_bounds__(128) void k_scan2(int nChunks) {
    __shared__ int s[128];
    int t = threadIdx.x;
    int v = (t < nChunks) ? g_part[t] : 0;
    s[t] = v;
    __syncthreads();
    for (int off = 1; off < 128; off <<= 1) {
        int x = (t >= off) ? s[t - off] : 0;
        __syncthreads();
        s[t] += x;
        __syncthreads();
    }
    if (t < nChunks) g_part[t] = s[t] - v;  // exclusive
}

__global__ void k_scan3(int n) {
    int i = blockIdx.x * blockDim.x + threadIdx.x;
    if (i >= n) return;
    int o = g_off[i] + g_part[i >> 10];
    g_off[i] = o;
    g_cur[i] = o;
}

__global__ void k_fill(const int* __restrict__ ei, int nEdges, int nNodes) {
    int e = blockIdx.x * blockDim.x + threadIdx.x;
    if (e >= nEdges) return;
    int src = __ldg(&ei[e]);
    int dst = __ldg(&ei[(size_t)nEdges + e]);
    if ((unsigned)src >= (unsigned)nNodes || (unsigned)dst >= (unsigned)nNodes) return;
    int pos = atomicAdd(&g_cur[dst], 1);
    if (pos < EMAX) g_csr[pos] = src;
}

// ===========================================================================
// Input projection: h = x @ w_in + b_in   [N,32] @ [32,64]  -> g_hA
// ===========================================================================
__global__ __launch_bounds__(256) void k_proj(const float* __restrict__ x,
                                              const float* __restrict__ w_in,
                                              const float* __restrict__ b_in,
                                              int nNodes) {
    __shared__ __align__(16) float sX[64 * IN_DIM];
    __shared__ __align__(16) float sW[IN_DIM * HID];
    int tid = threadIdx.x;
    int nb = blockIdx.x * 64;

    for (int i = tid; i < 64 * IN_DIM; i += 256) {
        int n = nb + i / IN_DIM;
        sX[i] = (n < nNodes) ? x[(size_t)nb * IN_DIM + i] : 0.f;
    }
    for (int i = tid; i < IN_DIM * HID; i += 256) sW[i] = w_in[i];
    __syncthreads();

    int fq = tid & 15, ng = tid >> 4;
    float acc[4][4];
    float4 bb = *reinterpret_cast<const float4*>(b_in + 4 * fq);
#pragma unroll
    for (int n = 0; n < 4; n++) {
        acc[n][0] = bb.x; acc[n][1] = bb.y; acc[n][2] = bb.z; acc[n][3] = bb.w;
    }
#pragma unroll
    for (int k = 0; k < IN_DIM; k += 4) {
        float4 w0 = *reinterpret_cast<const float4*>(&sW[(k + 0) * HID + 4 * fq]);
        float4 w1 = *reinterpret_cast<const float4*>(&sW[(k + 1) * HID + 4 * fq]);
        float4 w2 = *reinterpret_cast<const float4*>(&sW[(k + 2) * HID + 4 * fq]);
        float4 w3 = *reinterpret_cast<const float4*>(&sW[(k + 3) * HID + 4 * fq]);
#pragma unroll
        for (int n = 0; n < 4; n++) {
            float4 a = *reinterpret_cast<const float4*>(&sX[(ng * 4 + n) * IN_DIM + k]);
            acc[n][0] += a.x * w0.x + a.y * w1.x + a.z * w2.x + a.w * w3.x;
            acc[n][1] += a.x * w0.y + a.y * w1.y + a.z * w2.y + a.w * w3.y;
            acc[n][2] += a.x * w0.z + a.y * w1.z + a.z * w2.z + a.w * w3.z;
            acc[n][3] += a.x * w0.w + a.y * w1.w + a.z * w2.w + a.w * w3.w;
        }
    }
#pragma unroll
    for (int n = 0; n < 4; n++) {
        int node = nb + ng * 4 + n;
        if (node < nNodes)
            *reinterpret_cast<float4*>(&g_hA[(size_t)node * HID + 4 * fq]) =
                make_float4(acc[n][0], acc[n][1], acc[n][2], acc[n][3]);
    }
}

// ===========================================================================
// Shared 4x4-register-blocked GEMM tile core (round-3 proven FFMA version)
// ===========================================================================
__device__ __forceinline__ void gemm44(const float* __restrict__ sA,
                                       const float* __restrict__ sW,
                                       int fq, int ng, float acc[4][4]) {
#pragma unroll
    for (int k = 0; k < HID; k += 4) {
        float4 w0 = *reinterpret_cast<const float4*>(&sW[(k + 0) * HID + 4 * fq]);
        float4 w1 = *reinterpret_cast<const float4*>(&sW[(k + 1) * HID + 4 * fq]);
        float4 w2 = *reinterpret_cast<const float4*>(&sW[(k + 2) * HID + 4 * fq]);
        float4 w3 = *reinterpret_cast<const float4*>(&sW[(k + 3) * HID + 4 * fq]);
#pragma unroll
        for (int n = 0; n < 4; n++) {
            float4 a = *reinterpret_cast<const float4*>(&sA[(ng * 4 + n) * HID + k]);
            acc[n][0] += a.x * w0.x + a.y * w1.x + a.z * w2.x + a.w * w3.x;
            acc[n][1] += a.x * w0.y + a.y * w1.y + a.z * w2.y + a.w * w3.y;
            acc[n][2] += a.x * w0.z + a.y * w1.z + a.z * w2.z + a.w * w3.z;
            acc[n][3] += a.x * w0.w + a.y * w1.w + a.z * w2.w + a.w * w3.w;
        }
    }
}

// ===========================================================================
// Fused gather + GIN MLP (double-buffered: reads hin, writes hout):
//   agg = sum_{src in CSR(dst)} hin[src]
//   hout = relu(relu((hin+agg)w1+b1)w2+b2) + hin
// Last layer also pools: pooled[batch[n]] += hout[n]  (red.v4)
// ===========================================================================
__global__ __launch_bounds__(256) void k_mlp_gather(const float* __restrict__ hin,
                                                    float* __restrict__ hout,
                                                    const float* __restrict__ w1,
                                                    const float* __restrict__ b1,
                                                    const float* __restrict__ w2,
                                                    const float* __restrict__ b2,
                                                    const int* __restrict__ batch,
                                                    int isLast, int nNodes) {
    __shared__ __align__(16) float sW[HID * HID];   // 16 KB (w1 then w2)
    __shared__ __align__(16) float sIn[64 * HID];   // 16 KB
    __shared__ __align__(16) float sMid[64 * HID];  // 16 KB
    int tid = threadIdx.x;
    int nb = blockIdx.x * 64;

    for (int i = tid; i < HID * HID; i += 256) sW[i] = w1[i];

    // Gather: 16 groups x 16 lanes; group handles one node per pass (4 passes).
    {
        int grp = tid >> 4, lane = tid & 15;
#pragma unroll
        for (int pass = 0; pass < 4; pass++) {
            int nl = pass * 16 + grp;
            int node = nb + nl;
            float4 acc = make_float4(0.f, 0.f, 0.f, 0.f);
            if (node < nNodes) {
                size_t hb = (size_t)node * HID + 4 * lane;
                acc = *reinterpret_cast<const float4*>(&hin[hb]);   // self (h + agg)
                int s = __ldg(&g_off[node]);
                int e = s + __ldg(&g_deg[node]);
                for (int i = s; i < e; i++) {
                    int src = __ldg(&g_csr[i]);
                    float4 v = __ldg(reinterpret_cast<const float4*>(
                        &hin[(size_t)src * HID + 4 * lane]));
                    acc.x += v.x; acc.y += v.y; acc.z += v.z; acc.w += v.w;
                }
            }
            *reinterpret_cast<float4*>(&sIn[nl * HID + 4 * lane]) = acc;
        }
    }
    __syncthreads();

    int fq = tid & 15, ng = tid >> 4;
    float acc[4][4];

    // ---- phase 1: mid = relu(in @ w1 + b1) ----
    {
        float4 bb = *reinterpret_cast<const float4*>(b1 + 4 * fq);
#pragma unroll
        for (int n = 0; n < 4; n++) {
            acc[n][0] = bb.x; acc[n][1] = bb.y; acc[n][2] = bb.z; acc[n][3] = bb.w;
        }
        gemm44(sIn, sW, fq, ng, acc);
#pragma unroll
        for (int n = 0; n < 4; n++) {
            *reinterpret_cast<float4*>(&sMid[(ng * 4 + n) * HID + 4 * fq]) =
                make_float4(fmaxf(acc[n][0], 0.f), fmaxf(acc[n][1], 0.f),
                            fmaxf(acc[n][2], 0.f), fmaxf(acc[n][3], 0.f));
        }
    }
    __syncthreads();

    for (int i = tid; i < HID * HID; i += 256) sW[i] = w2[i];
    __syncthreads();

    // ---- phase 2: hout = relu(mid @ w2 + b2) + hin  (+ pool on last layer) ----
    {
        float4 bb = *reinterpret_cast<const float4*>(b2 + 4 * fq);
#pragma unroll
        for (int n = 0; n < 4; n++) {
            acc[n][0] = bb.x; acc[n][1] = bb.y; acc[n][2] = bb.z; acc[n][3] = bb.w;
        }
        gemm44(sMid, sW, fq, ng, acc);
#pragma unroll
        for (int n = 0; n < 4; n++) {
            int node = nb + ng * 4 + n;
            if (node < nNodes) {
                size_t idx = (size_t)node * HID + 4 * fq;
                float4 skip = *reinterpret_cast<const float4*>(&hin[idx]);
                float4 r = make_float4(fmaxf(acc[n][0], 0.f) + skip.x,
                                       fmaxf(acc[n][1], 0.f) + skip.y,
                                       fmaxf(acc[n][2], 0.f) + skip.z,
                                       fmaxf(acc[n][3], 0.f) + skip.w);
                *reinterpret_cast<float4*>(&hout[idx]) = r;
                if (isLast) {
                    int g = __ldg(&batch[node]);
                    if ((unsigned)g < NGRAPHS)
                        red_add_v4(&g_pooled[g * HID + 4 * fq], r);
                }
            }
        }
    }
}

// ===========================================================================
// Final: out = pooled @ w_fc + b_fc   [128,64] @ [64,32]
// ===========================================================================
__global__ __launch_bounds__(256) void k_final(const float* __restrict__ w_fc,
                                               const float* __restrict__ b_fc,
                                               float* __restrict__ out) {
    int t = blockIdx.x * blockDim.x + threadIdx.x;
    if (t >= NGRAPHS * LAT) return;
    int g = t >> 5;
    int l = t & 31;
    float acc = b_fc[l];
#pragma unroll
    for (int k = 0; k < HID; k++)
        acc += g_pooled[g * HID + k] * w_fc[k * LAT + l];
    out[t] = acc;
}

// ===========================================================================
// Launch
// ===========================================================================
extern "C" void kernel_launch(void* const* d_in, const int* in_sizes, int n_in,
                              void* d_out, int out_size) {
    const float* x    = (const float*)d_in[0];
    const int*   ei   = (const int*)d_in[1];
    const int*   batch= (const int*)d_in[2];
    const float* w_in = (const float*)d_in[3];
    const float* b_in = (const float*)d_in[4];
    const float* w1   = (const float*)d_in[5];
    const float* b1   = (const float*)d_in[6];
    const float* w2   = (const float*)d_in[7];
    const float* b2   = (const float*)d_in[8];
    const float* w_fc = (const float*)d_in[9];
    const float* b_fc = (const float*)d_in[10];
    float* out = (float*)d_out;

    int nNodes = in_sizes[0] / IN_DIM;
    int nEdges = in_sizes[1] / 2;
    if (nNodes > NMAX) nNodes = NMAX;
    if (nEdges > EMAX) nEdges = EMAX;

    int nodeBlocks = (nNodes + 63) / 64;
    int edgeBlocks = (nEdges + 255) / 256;
    int nThreadBlocks = (nNodes + 255) / 256;
    int nChunks = (nNodes + 1023) / 1024;

    // Resolve device-global buffer addresses for ping-pong
    float *hA, *hB;
    cudaGetSymbolAddress((void**)&hA, g_hA);
    cudaGetSymbolAddress((void**)&hB, g_hB);

    // CSR build (reused across all 3 layers)
    k_zero_pooled<<<(NGRAPHS * HID / 4 + 255) / 256, 256>>>();
    k_zero_deg<<<nThreadBlocks, 256>>>(nNodes);
    k_hist<<<edgeBlocks, 256>>>(ei, nEdges, nNodes);
    k_scan1<<<nChunks, 1024>>>(nNodes);
    k_scan2<<<1, 128>>>(nChunks);
    k_scan3<<<nThreadBlocks, 256>>>(nNodes);
    k_fill<<<edgeBlocks, 256>>>(ei, nEdges, nNodes);

    k_proj<<<nodeBlocks, 256>>>(x, w_in, b_in, nNodes);

    const float* cur = hA;
    float* nxt = hB;
    for (int i = 0; i < 3; i++) {
        k_mlp_gather<<<nodeBlocks, 256>>>(
            cur, nxt,
            w1 + (size_t)i * HID * HID, b1 + (size_t)i * HID,
            w2 + (size_t)i * HID * HID, b2 + (size_t)i * HID,
            batch, (i == 2) ? 1 : 0, nNodes);
        const float* tmp = nxt;
        nxt = (float*)cur;
        cur = tmp;
    }

    k_final<<<(NGRAPHS * LAT + 255) / 256, 256>>>(w_fc, b_fc, out);
}

// round 15
// speedup vs baseline: 2.0504x; 1.0698x over previous
#include <cuda_runtime.h>
#include <cstdint>

// Problem constants
#define NMAX    100000
#define EMAX    1000000
#define IN_DIM  32
#define HID     64
#define NGRAPHS 128
#define LAT     32

#define LDAA 68     // A-tile row stride (floats): conflict-free A-fragment loads
#define LDAW 72     // W-tile row stride (floats): conflict-free B-fragment loads
// dynamic smem: sInHi | sInLo | sWHi | sWLo
#define OFF_INHI 0
#define OFF_INLO (64 * LDAA)
#define OFF_WHI  (2 * 64 * LDAA)
#define OFF_WLO  (2 * 64 * LDAA + 64 * LDAW)
#define SMEM_FLOATS (2 * 64 * LDAA + 2 * 64 * LDAW)
#define SMEM_BYTES (SMEM_FLOATS * 4)   // 71680

// Scratch (device globals — allocation-free rule)
__device__ __align__(16) float g_hA[(size_t)NMAX * HID];
__device__ __align__(16) float g_hB[(size_t)NMAX * HID];
__device__ __align__(16) float g_pooled[NGRAPHS * HID];
__device__ int g_deg[NMAX];
__device__ int g_off[NMAX];
__device__ int g_cur[NMAX];
__device__ int g_csr[EMAX];
__device__ int g_part[128];

__device__ __forceinline__ void red_add_v2(float* p, float2 v) {
    asm volatile("red.global.add.v2.f32 [%0], {%1,%2};"
                 :: "l"(p), "f"(v.x), "f"(v.y) : "memory");
}

// 3xTF32 split: hi = tf32(x), lo = tf32(x - hi)
__device__ __forceinline__ float2 tf32_split(float x) {
    uint32_t h;
    asm("cvt.rna.tf32.f32 %0, %1;" : "=r"(h) : "f"(x));
    float hf = __uint_as_float(h);
    float lo = x - hf;
    uint32_t l;
    asm("cvt.rna.tf32.f32 %0, %1;" : "=r"(l) : "f"(lo));
    return make_float2(hf, __uint_as_float(l));
}

// m16n8k8 tf32 MMA (HMMA pipe; baseline PTX, compiles for sm_103 non-a)
__device__ __forceinline__ void hmma(float c[4],
                                     uint32_t a0, uint32_t a1, uint32_t a2, uint32_t a3,
                                     uint32_t b0, uint32_t b1) {
    asm("mma.sync.aligned.m16n8k8.row.col.f32.tf32.tf32.f32 "
        "{%0,%1,%2,%3}, {%4,%5,%6,%7}, {%8,%9}, {%0,%1,%2,%3};"
        : "+f"(c[0]), "+f"(c[1]), "+f"(c[2]), "+f"(c[3])
        : "r"(a0), "r"(a1), "r"(a2), "r"(a3), "r"(b0), "r"(b1));
}

// ===========================================================================
// Zero / CSR-build kernels
// ===========================================================================
__global__ void k_zero_pooled() {
    int i = blockIdx.x * blockDim.x + threadIdx.x;
    if (i < NGRAPHS * HID / 4)
        reinterpret_cast<float4*>(g_pooled)[i] = make_float4(0.f, 0.f, 0.f, 0.f);
}

__global__ void k_zero_deg(int n) {
    int i = blockIdx.x * blockDim.x + threadIdx.x;
    if (i < n) g_deg[i] = 0;
}

__global__ void k_hist(const int* __restrict__ ei, int nEdges, int nNodes) {
    int e = blockIdx.x * blockDim.x + threadIdx.x;
    if (e >= nEdges) return;
    int src = __ldg(&ei[e]);
    int dst = __ldg(&ei[(size_t)nEdges + e]);
    if ((unsigned)src >= (unsigned)nNodes || (unsigned)dst >= (unsigned)nNodes) return;
    atomicAdd(&g_deg[dst], 1);
}

__global__ __launch_bounds__(1024) void k_scan1(int n) {
    __shared__ int s[1024];
    int t = threadIdx.x;
    int i = blockIdx.x * 1024 + t;
    int v = (i < n) ? g_deg[i] : 0;
    s[t] = v;
    __syncthreads();
    for (int off = 1; off < 1024; off <<= 1) {
        int x = (t >= off) ? s[t - off] : 0;
        __syncthreads();
        s[t] += x;
        __syncthreads();
    }
    if (i < n) g_off[i] = s[t] - v;
    if (t == 1023) g_part[blockIdx.x] = s[1023];
}

__global__ __launch_bounds__(128) void k_scan2(int nChunks) {
    __shared__ int s[128];
    int t = threadIdx.x;
    int v = (t < nChunks) ? g_part[t] : 0;
    s[t] = v;
    __syncthreads();
    for (int off = 1; off < 128; off <<= 1) {
        int x = (t >= off) ? s[t - off] : 0;
        __syncthreads();
        s[t] += x;
        __syncthreads();
    }
    if (t < nChunks) g_part[t] = s[t] - v;
}

__global__ void k_scan3(int n) {
    int i = blockIdx.x * blockDim.x + threadIdx.x;
    if (i >= n) return;
    int o = g_off[i] + g_part[i >> 10];
    g_off[i] = o;
    g_cur[i] = o;
}

__global__ void k_fill(const int* __restrict__ ei, int nEdges, int nNodes) {
    int e = blockIdx.x * blockDim.x + threadIdx.x;
    if (e >= nEdges) return;
    int src = __ldg(&ei[e]);
    int dst = __ldg(&ei[(size_t)nEdges + e]);
    if ((unsigned)src >= (unsigned)nNodes || (unsigned)dst >= (unsigned)nNodes) return;
    int pos = atomicAdd(&g_cur[dst], 1);
    if (pos < EMAX) g_csr[pos] = src;
}

// ===========================================================================
// Input projection: h = x @ w_in + b_in   [N,32] @ [32,64]  -> g_hA
// ===========================================================================
__global__ __launch_bounds__(256) void k_proj(const float* __restrict__ x,
                                              const float* __restrict__ w_in,
                                              const float* __restrict__ b_in,
                                              int nNodes) {
    __shared__ __align__(16) float sX[64 * IN_DIM];
    __shared__ __align__(16) float sW[IN_DIM * HID];
    int tid = threadIdx.x;
    int nb = blockIdx.x * 64;

    for (int i = tid; i < 64 * IN_DIM; i += 256) {
        int n = nb + i / IN_DIM;
        sX[i] = (n < nNodes) ? x[(size_t)nb * IN_DIM + i] : 0.f;
    }
    for (int i = tid; i < IN_DIM * HID; i += 256) sW[i] = w_in[i];
    __syncthreads();

    int fq = tid & 15, ng = tid >> 4;
    float acc[4][4];
    float4 bb = *reinterpret_cast<const float4*>(b_in + 4 * fq);
#pragma unroll
    for (int n = 0; n < 4; n++) {
        acc[n][0] = bb.x; acc[n][1] = bb.y; acc[n][2] = bb.z; acc[n][3] = bb.w;
    }
#pragma unroll
    for (int k = 0; k < IN_DIM; k += 4) {
        float4 w0 = *reinterpret_cast<const float4*>(&sW[(k + 0) * HID + 4 * fq]);
        float4 w1 = *reinterpret_cast<const float4*>(&sW[(k + 1) * HID + 4 * fq]);
        float4 w2 = *reinterpret_cast<const float4*>(&sW[(k + 2) * HID + 4 * fq]);
        float4 w3 = *reinterpret_cast<const float4*>(&sW[(k + 3) * HID + 4 * fq]);
#pragma unroll
        for (int n = 0; n < 4; n++) {
            float4 a = *reinterpret_cast<const float4*>(&sX[(ng * 4 + n) * IN_DIM + k]);
            acc[n][0] += a.x * w0.x + a.y * w1.x + a.z * w2.x + a.w * w3.x;
            acc[n][1] += a.x * w0.y + a.y * w1.y + a.z * w2.y + a.w * w3.y;
            acc[n][2] += a.x * w0.z + a.y * w1.z + a.z * w2.z + a.w * w3.z;
            acc[n][3] += a.x * w0.w + a.y * w1.w + a.z * w2.w + a.w * w3.w;
        }
    }
#pragma unroll
    for (int n = 0; n < 4; n++) {
        int node = nb + ng * 4 + n;
        if (node < nNodes)
            *reinterpret_cast<float4*>(&g_hA[(size_t)node * HID + 4 * fq]) =
                make_float4(acc[n][0], acc[n][1], acc[n][2], acc[n][3]);
    }
}

// ===========================================================================
// 3xTF32 tensor-core GEMM core: one warp computes 4 m16n8 C-tiles
// (M-tile m, N-tiles nbase+8j), K=64 in 8 steps of 8.
// ===========================================================================
__device__ __forceinline__ void tcgemm(float c[4][4],
                                       const float* __restrict__ sAhi,
                                       const float* __restrict__ sAlo,
                                       const float* __restrict__ sBhi,
                                       const float* __restrict__ sBlo,
                                       int m, int nbase, int gid, int tig) {
#pragma unroll
    for (int s = 0; s < 8; s++) {
        int k = 8 * s;
        int ar0 = (m + gid) * LDAA + k + tig;
        int ar1 = ar0 + 8 * LDAA;
        uint32_t ah0 = __float_as_uint(sAhi[ar0]);
        uint32_t ah1 = __float_as_uint(sAhi[ar1]);
        uint32_t ah2 = __float_as_uint(sAhi[ar0 + 4]);
        uint32_t ah3 = __float_as_uint(sAhi[ar1 + 4]);
        uint32_t al0 = __float_as_uint(sAlo[ar0]);
        uint32_t al1 = __float_as_uint(sAlo[ar1]);
        uint32_t al2 = __float_as_uint(sAlo[ar0 + 4]);
        uint32_t al3 = __float_as_uint(sAlo[ar1 + 4]);
#pragma unroll
        for (int j = 0; j < 4; j++) {
            int bo = (k + tig) * LDAW + nbase + 8 * j + gid;
            uint32_t bh0 = __float_as_uint(sBhi[bo]);
            uint32_t bh1 = __float_as_uint(sBhi[bo + 4 * LDAW]);
            uint32_t bl0 = __float_as_uint(sBlo[bo]);
            uint32_t bl1 = __float_as_uint(sBlo[bo + 4 * LDAW]);
            hmma(c[j], ah0, ah1, ah2, ah3, bh0, bh1);
            hmma(c[j], ah0, ah1, ah2, ah3, bl0, bl1);
            hmma(c[j], al0, al1, al2, al3, bh0, bh1);
        }
    }
}

// ===========================================================================
// Fused gather + GIN MLP, tensor-core version (reads hin, writes hout):
//   agg = sum_{src in CSR(dst)} hin[src]
//   hout = relu(relu((hin+agg)w1+b1)w2+b2) + hin ; last layer pools.
// ===========================================================================
__global__ __launch_bounds__(256) void k_mlp_tc(const float* __restrict__ hin,
                                                float* __restrict__ hout,
                                                const float* __restrict__ w1,
                                                const float* __restrict__ b1,
                                                const float* __restrict__ w2,
                                                const float* __restrict__ b2,
                                                const int* __restrict__ batch,
                                                int isLast, int nNodes) {
    extern __shared__ __align__(16) float sm[];
    float* sInHi = sm + OFF_INHI;
    float* sInLo = sm + OFF_INLO;
    float* sWHi  = sm + OFF_WHI;
    float* sWLo  = sm + OFF_WLO;
    int tid = threadIdx.x;
    int nb = blockIdx.x * 64;

    // stage w1 (split hi/lo)
#pragma unroll
    for (int j = 0; j < 4; j++) {
        int idx = tid + j * 256;              // float4 index, 1024 total
        int k = idx >> 4;
        int n4 = (idx & 15) << 2;
        float4 w = __ldg(reinterpret_cast<const float4*>(w1) + idx);
        float2 s0 = tf32_split(w.x), s1 = tf32_split(w.y),
               s2 = tf32_split(w.z), s3 = tf32_split(w.w);
        *(float4*)&sWHi[k * LDAW + n4] = make_float4(s0.x, s1.x, s2.x, s3.x);
        *(float4*)&sWLo[k * LDAW + n4] = make_float4(s0.y, s1.y, s2.y, s3.y);
    }

    // gather: 16 groups x 16 lanes; 4 passes
    {
        int grp = tid >> 4, lane16 = tid & 15;
#pragma unroll
        for (int pass = 0; pass < 4; pass++) {
            int nl = pass * 16 + grp;
            int node = nb + nl;
            float4 acc = make_float4(0.f, 0.f, 0.f, 0.f);
            if (node < nNodes) {
                acc = *reinterpret_cast<const float4*>(
                    &hin[(size_t)node * HID + 4 * lane16]);
                int s = __ldg(&g_off[node]);
                int e = s + __ldg(&g_deg[node]);
                for (int i = s; i < e; i++) {
                    int src = __ldg(&g_csr[i]);
                    float4 v = __ldg(reinterpret_cast<const float4*>(
                        &hin[(size_t)src * HID + 4 * lane16]));
                    acc.x += v.x; acc.y += v.y; acc.z += v.z; acc.w += v.w;
                }
            }
            float2 s0 = tf32_split(acc.x), s1 = tf32_split(acc.y),
                   s2 = tf32_split(acc.z), s3 = tf32_split(acc.w);
            *(float4*)&sInHi[nl * LDAA + 4 * lane16] = make_float4(s0.x, s1.x, s2.x, s3.x);
            *(float4*)&sInLo[nl * LDAA + 4 * lane16] = make_float4(s0.y, s1.y, s2.y, s3.y);
        }
    }
    __syncthreads();

    int wid = tid >> 5, lane = tid & 31;
    int gid = lane >> 2, tig = lane & 3;
    int m = (wid & 3) * 16;
    int nbase = (wid >> 2) * 32;

    float c[4][4];
    // ---- phase 1: mid = relu(in @ w1 + b1) ----
#pragma unroll
    for (int j = 0; j < 4; j++) {
        float2 bb = __ldg(reinterpret_cast<const float2*>(&b1[nbase + 8 * j + 2 * tig]));
        c[j][0] = bb.x; c[j][1] = bb.y; c[j][2] = bb.x; c[j][3] = bb.y;
    }
    tcgemm(c, sInHi, sInLo, sWHi, sWLo, m, nbase, gid, tig);
    __syncthreads();

    // epi1: relu + split back into A tiles; stage w2 into W tiles
#pragma unroll
    for (int j = 0; j < 4; j++) {
        int n0 = nbase + 8 * j + 2 * tig;
        int r0 = m + gid, r1 = r0 + 8;
        float2 s0 = tf32_split(fmaxf(c[j][0], 0.f));
        float2 s1 = tf32_split(fmaxf(c[j][1], 0.f));
        float2 s2 = tf32_split(fmaxf(c[j][2], 0.f));
        float2 s3 = tf32_split(fmaxf(c[j][3], 0.f));
        *(float2*)&sInHi[r0 * LDAA + n0] = make_float2(s0.x, s1.x);
        *(float2*)&sInLo[r0 * LDAA + n0] = make_float2(s0.y, s1.y);
        *(float2*)&sInHi[r1 * LDAA + n0] = make_float2(s2.x, s3.x);
        *(float2*)&sInLo[r1 * LDAA + n0] = make_float2(s2.y, s3.y);
    }
#pragma unroll
    for (int j = 0; j < 4; j++) {
        int idx = tid + j * 256;
        int k = idx >> 4;
        int n4 = (idx & 15) << 2;
        float4 w = __ldg(reinterpret_cast<const float4*>(w2) + idx);
        float2 s0 = tf32_split(w.x), s1 = tf32_split(w.y),
               s2 = tf32_split(w.z), s3 = tf32_split(w.w);
        *(float4*)&sWHi[k * LDAW + n4] = make_float4(s0.x, s1.x, s2.x, s3.x);
        *(float4*)&sWLo[k * LDAW + n4] = make_float4(s0.y, s1.y, s2.y, s3.y);
    }
    __syncthreads();

    // ---- phase 2: hout = relu(mid @ w2 + b2) + hin ----
#pragma unroll
    for (int j = 0; j < 4; j++) {
        float2 bb = __ldg(reinterpret_cast<const float2*>(&b2[nbase + 8 * j + 2 * tig]));
        c[j][0] = bb.x; c[j][1] = bb.y; c[j][2] = bb.x; c[j][3] = bb.y;
    }
    tcgemm(c, sInHi, sInLo, sWHi, sWLo, m, nbase, gid, tig);

    // epi2: relu + skip + store (+ pool on last layer)
#pragma unroll
    for (int j = 0; j < 4; j++) {
        int n0 = nbase + 8 * j + 2 * tig;
#pragma unroll
        for (int half = 0; half < 2; half++) {
            int r = m + gid + 8 * half;
            int node = nb + r;
            if (node < nNodes) {
                float cx = c[j][2 * half], cy = c[j][2 * half + 1];
                size_t gbi = (size_t)node * HID + n0;
                float2 skip = __ldg(reinterpret_cast<const float2*>(&hin[gbi]));
                float2 r2 = make_float2(fmaxf(cx, 0.f) + skip.x,
                                        fmaxf(cy, 0.f) + skip.y);
                *reinterpret_cast<float2*>(&hout[gbi]) = r2;
                if (isLast) {
                    int g = __ldg(&batch[node]);
                    if ((unsigned)g < NGRAPHS)
                        red_add_v2(&g_pooled[g * HID + n0], r2);
                }
            }
        }
    }
}

// ===========================================================================
// Final: out = pooled @ w_fc + b_fc   [128,64] @ [64,32]
// ===========================================================================
__global__ __launch_bounds__(256) void k_final(const float* __restrict__ w_fc,
                                               const float* __restrict__ b_fc,
                                               float* __restrict__ out) {
    int t = blockIdx.x * blockDim.x + threadIdx.x;
    if (t >= NGRAPHS * LAT) return;
    int g = t >> 5;
    int l = t & 31;
    float acc = b_fc[l];
#pragma unroll
    for (int k = 0; k < HID; k++)
        acc += g_pooled[g * HID + k] * w_fc[k * LAT + l];
    out[t] = acc;
}

// ===========================================================================
// Launch
// ===========================================================================
extern "C" void kernel_launch(void* const* d_in, const int* in_sizes, int n_in,
                              void* d_out, int out_size) {
    const float* x    = (const float*)d_in[0];
    const int*   ei   = (const int*)d_in[1];
    const int*   batch= (const int*)d_in[2];
    const float* w_in = (const float*)d_in[3];
    const float* b_in = (const float*)d_in[4];
    const float* w1   = (const float*)d_in[5];
    const float* b1   = (const float*)d_in[6];
    const float* w2   = (const float*)d_in[7];
    const float* b2   = (const float*)d_in[8];
    const float* w_fc = (const float*)d_in[9];
    const float* b_fc = (const float*)d_in[10];
    float* out = (float*)d_out;

    int nNodes = in_sizes[0] / IN_DIM;
    int nEdges = in_sizes[1] / 2;
    if (nNodes > NMAX) nNodes = NMAX;
    if (nEdges > EMAX) nEdges = EMAX;

    int nodeBlocks = (nNodes + 63) / 64;
    int edgeBlocks = (nEdges + 255) / 256;
    int nThreadBlocks = (nNodes + 255) / 256;
    int nChunks = (nNodes + 1023) / 1024;

    static int smemSet = 0;
    if (!smemSet) {
        cudaFuncSetAttribute(k_mlp_tc, cudaFuncAttributeMaxDynamicSharedMemorySize,
                             SMEM_BYTES);
        smemSet = 1;
    }

    float *hA, *hB;
    cudaGetSymbolAddress((void**)&hA, g_hA);
    cudaGetSymbolAddress((void**)&hB, g_hB);

    // CSR build (reused across all 3 layers)
    k_zero_pooled<<<(NGRAPHS * HID / 4 + 255) / 256, 256>>>();
    k_zero_deg<<<nThreadBlocks, 256>>>(nNodes);
    k_hist<<<edgeBlocks, 256>>>(ei, nEdges, nNodes);
    k_scan1<<<nChunks, 1024>>>(nNodes);
    k_scan2<<<1, 128>>>(nChunks);
    k_scan3<<<nThreadBlocks, 256>>>(nNodes);
    k_fill<<<edgeBlocks, 256>>>(ei, nEdges, nNodes);

    k_proj<<<nodeBlocks, 256>>>(x, w_in, b_in, nNodes);

    const float* cur = hA;
    float* nxt = hB;
    for (int i = 0; i < 3; i++) {
        k_mlp_tc<<<nodeBlocks, 256, SMEM_BYTES>>>(
            cur, nxt,
            w1 + (size_t)i * HID * HID, b1 + (size_t)i * HID,
            w2 + (size_t)i * HID * HID, b2 + (size_t)i * HID,
            batch, (i == 2) ? 1 : 0, nNodes);
        const float* tmp = nxt;
        nxt = (float*)cur;
        cur = tmp;
    }

    k_final<<<(NGRAPHS * LAT + 255) / 256, 256>>>(w_fc, b_fc, out);
}